// round 3
// baseline (speedup 1.0000x reference)
#include <cuda_runtime.h>
#include <math.h>

#define Bdim 128
#define Pdim 256
#define PIXdim 256
#define Ddim 512
#define Cdim 10

#define NSTATE (Bdim*Pdim*Ddim)   // 16,777,216
#define NATTN  (Bdim*Pdim*Pdim)   // 8,388,608
#define NPART  4096

typedef unsigned long long ull;

static __device__ float g_re0[NSTATE];
static __device__ float g_im0[NSTATE];
static __device__ float g_re1[NSTATE];
static __device__ float g_im1[NSTATE];
static __device__ float g_u_re[NSTATE];
static __device__ float g_u_im[NSTATE];
static __device__ float g_attn[NATTN];
static __device__ float g_pool_re[Bdim*Ddim];
static __device__ float g_pool_im[Bdim*Ddim];
static __device__ float g_cd[Ddim], g_sd[Ddim], g_cv[Ddim], g_sv[Ddim];
static __device__ double g_part_d[NPART];
static __device__ double g_part_n[NPART];
static __device__ int g_active;
static __device__ int g_cur;

// ---------------------------------------------------------------- packed f32x2 helpers
__device__ __forceinline__ ull ldp(const float* p) {
    float2 v = *reinterpret_cast<const float2*>(p);
    ull r; asm("mov.b64 %0, {%1,%2};" : "=l"(r) : "f"(v.x), "f"(v.y)); return r;
}
__device__ __forceinline__ ull dup2(float a) {
    ull r; asm("mov.b64 %0, {%1,%1};" : "=l"(r) : "f"(a)); return r;
}
__device__ __forceinline__ float2 up(ull v) {
    float2 r; asm("mov.b64 {%0,%1}, %2;" : "=f"(r.x), "=f"(r.y) : "l"(v)); return r;
}
__device__ __forceinline__ void fma2(ull& d, ull a, ull b) {
    asm("fma.rn.f32x2 %0, %1, %2, %0;" : "+l"(d) : "l"(a), "l"(b));
}

// ---------------------------------------------------------------- prep
__global__ void k_prep(const float* __restrict__ qr, const float* __restrict__ kr,
                       const float* __restrict__ vr) {
    int d = threadIdx.x;
    if (d < Ddim) {
        float cq, sq, ck, sk, cv, sv;
        sincosf(qr[d], &sq, &cq);
        sincosf(kr[d], &sk, &ck);
        sincosf(vr[d], &sv, &cv);
        g_cd[d] = cq*ck + sq*sk;
        g_sd[d] = sq*ck - cq*sk;
        g_cv[d] = cv;
        g_sv[d] = sv;
    }
    if (d == 0) { g_active = 1; g_cur = 0; }
}

// ---------------------------------------------------------------- proj: state = tanh(x@Wp^T+bp) * e^{i phase}
__global__ void k_proj(const float* __restrict__ x, const float* __restrict__ Wp,
                       const float* __restrict__ bp) {
    __shared__ float As[16][68];
    __shared__ float Bs[16][68];
    const int tid = threadIdx.x;
    const int m0 = blockIdx.y * 64, n0 = blockIdx.x * 64;
    const int tm = (tid >> 4) * 4, tn = (tid & 15) * 4;
    const int lk = tid & 15, lr = tid >> 4;
    float acc[4][4] = {};
    for (int k0 = 0; k0 < PIXdim; k0 += 16) {
        #pragma unroll
        for (int i = 0; i < 4; i++) {
            As[lk][lr + 16*i] = x [(size_t)(m0 + lr + 16*i) * PIXdim + (k0 + lk)];
            Bs[lk][lr + 16*i] = Wp[(size_t)(n0 + lr + 16*i) * PIXdim + (k0 + lk)];
        }
        __syncthreads();
        #pragma unroll
        for (int kk = 0; kk < 16; kk++) {
            float a[4], b[4];
            #pragma unroll
            for (int i = 0; i < 4; i++) { a[i] = As[kk][tm+i]; b[i] = Bs[kk][tn+i]; }
            #pragma unroll
            for (int i = 0; i < 4; i++)
                #pragma unroll
                for (int j = 0; j < 4; j++)
                    acc[i][j] = fmaf(a[i], b[j], acc[i][j]);
        }
        __syncthreads();
    }
    const float PI = 3.14159265358979323846f;
    #pragma unroll
    for (int j = 0; j < 4; j++) {
        int n = n0 + tn + j;
        float freq = 1.0f / powf(10000.0f, (float)n / (float)Ddim);
        float bpv = bp[n];
        #pragma unroll
        for (int i = 0; i < 4; i++) {
            int m = m0 + tm + i;
            int p = m & (Pdim - 1);
            float t = tanhf(acc[i][j] + bpv);
            float ph = ((float)p * freq) * PI;
            float s, c;
            sincosf(ph, &s, &c);
            size_t idx = (size_t)m * Ddim + n;
            g_re0[idx] = t * c;
            g_im0[idx] = t * s;
        }
    }
}

// ---------------------------------------------------------------- QK^H real part * scale (FFMA2, n-pairs)
// tile: 64 p-rows x 256 q-cols (full row), K=512
__global__ void __launch_bounds__(256, 2) k_qk() {
    __shared__ float Ar[16][66], Ai[16][66];
    __shared__ float Br[16][258], Bi[16][258];
    const int tid = threadIdx.x;
    const int tx = tid & 15, ty = tid >> 4;
    const int b = blockIdx.z;
    const int p0 = blockIdx.y * 64;
    const float* __restrict__ sre = (g_cur ? g_re1 : g_re0) + (size_t)b * Pdim * Ddim;
    const float* __restrict__ sim = (g_cur ? g_im1 : g_im0) + (size_t)b * Pdim * Ddim;

    ull acc[4][8];
    #pragma unroll
    for (int i = 0; i < 4; i++)
        #pragma unroll
        for (int q = 0; q < 8; q++) acc[i][q] = 0ULL;

    const int fm = tid >> 2;          // 0..63
    const int kc = (tid & 3) * 4;     // 0,4,8,12

    for (int k0 = 0; k0 < Ddim; k0 += 16) {
        // A: rotated p-rows, transposed [k][p]
        {
            float4 r4 = *reinterpret_cast<const float4*>(&sre[(size_t)(p0+fm)*Ddim + k0 + kc]);
            float4 i4 = *reinterpret_cast<const float4*>(&sim[(size_t)(p0+fm)*Ddim + k0 + kc]);
            float rev[4] = {r4.x, r4.y, r4.z, r4.w};
            float imv[4] = {i4.x, i4.y, i4.z, i4.w};
            #pragma unroll
            for (int e = 0; e < 4; e++) {
                int d = k0 + kc + e;
                float cd = g_cd[d], sd = g_sd[d];
                Ar[kc+e][fm] = rev[e] * cd - imv[e] * sd;
                Ai[kc+e][fm] = rev[e] * sd + imv[e] * cd;
            }
        }
        // B: raw q-rows transposed [k][q] (4 passes over q)
        #pragma unroll
        for (int j = 0; j < 4; j++) {
            int q = 64*j + fm;
            float4 r4 = *reinterpret_cast<const float4*>(&sre[(size_t)q*Ddim + k0 + kc]);
            float4 i4 = *reinterpret_cast<const float4*>(&sim[(size_t)q*Ddim + k0 + kc]);
            Br[kc+0][q] = r4.x; Br[kc+1][q] = r4.y; Br[kc+2][q] = r4.z; Br[kc+3][q] = r4.w;
            Bi[kc+0][q] = i4.x; Bi[kc+1][q] = i4.y; Bi[kc+2][q] = i4.z; Bi[kc+3][q] = i4.w;
        }
        __syncthreads();
        #pragma unroll 4
        for (int kk = 0; kk < 16; kk++) {
            ull ar2[4], ai2[4];
            #pragma unroll
            for (int i = 0; i < 4; i++) {
                ar2[i] = dup2(Ar[kk][ty*4+i]);
                ai2[i] = dup2(Ai[kk][ty*4+i]);
            }
            #pragma unroll
            for (int q = 0; q < 8; q++) {
                ull brd = ldp(&Br[kk][16*tx + 2*q]);
                ull bid = ldp(&Bi[kk][16*tx + 2*q]);
                #pragma unroll
                for (int i = 0; i < 4; i++) {
                    fma2(acc[i][q], ar2[i], brd);
                    fma2(acc[i][q], ai2[i], bid);
                }
            }
        }
        __syncthreads();
    }
    const float SCALE = 0.3535533905932738f;  // 8/sqrt(512)
    float* out = g_attn + (size_t)b * Pdim * Pdim;
    #pragma unroll
    for (int i = 0; i < 4; i++) {
        int p = p0 + ty*4 + i;
        float vals[16];
        #pragma unroll
        for (int q = 0; q < 8; q++) {
            float2 v = up(acc[i][q]);
            vals[2*q]   = v.x * SCALE;
            vals[2*q+1] = v.y * SCALE;
        }
        float* po = &out[(size_t)p * Pdim + 16*tx];
        #pragma unroll
        for (int j = 0; j < 4; j++)
            *reinterpret_cast<float4*>(po + 4*j) = *reinterpret_cast<float4*>(&vals[4*j]);
    }
}

// ---------------------------------------------------------------- softmax over rows of length 256
__global__ void k_softmax() {
    const int row = blockIdx.x;
    const int tid = threadIdx.x;
    float* a = g_attn + (size_t)row * Pdim;
    float v = a[tid];
    __shared__ float red[256];
    red[tid] = v;
    __syncthreads();
    for (int s = 128; s > 0; s >>= 1) {
        if (tid < s) red[tid] = fmaxf(red[tid], red[tid + s]);
        __syncthreads();
    }
    float mx = red[0];
    __syncthreads();
    float e = expf(v - mx);
    red[tid] = e;
    __syncthreads();
    for (int s = 128; s > 0; s >>= 1) {
        if (tid < s) red[tid] += red[tid + s];
        __syncthreads();
    }
    a[tid] = e / red[0];
}

// ---------------------------------------------------------------- u = prev + e^{iv} * (attn @ state) (FFMA2, n-pairs)
// tile: 64 p-rows x 128 d-cols, K=256
__global__ void __launch_bounds__(256, 2) k_av() {
    __shared__ float At[16][66];
    __shared__ float Bre[16][132], Bim[16][132];
    const int tid = threadIdx.x;
    const int tx = tid & 15, ty = tid >> 4;
    const int b = blockIdx.z;
    const int p0 = blockIdx.y * 64, d0 = blockIdx.x * 128;
    const float* __restrict__ sre = (g_cur ? g_re1 : g_re0) + (size_t)b * Pdim * Ddim;
    const float* __restrict__ sim = (g_cur ? g_im1 : g_im0) + (size_t)b * Pdim * Ddim;
    const float* __restrict__ at  = g_attn + (size_t)b * Pdim * Pdim;

    ull ar[4][4], ai[4][4];
    #pragma unroll
    for (int i = 0; i < 4; i++)
        #pragma unroll
        for (int q = 0; q < 4; q++) { ar[i][q] = 0ULL; ai[i][q] = 0ULL; }

    const int fm = tid >> 2;          // 0..63
    const int kc = (tid & 3) * 4;     // 0,4,8,12
    const int bk = tid >> 4;          // 0..15
    const int cs = (tid & 15) * 8;    // 0..120

    for (int k0 = 0; k0 < Pdim; k0 += 16) {
        // A: attn transposed [k][p]
        {
            float4 a4 = *reinterpret_cast<const float4*>(&at[(size_t)(p0+fm)*Pdim + k0 + kc]);
            At[kc+0][fm] = a4.x; At[kc+1][fm] = a4.y; At[kc+2][fm] = a4.z; At[kc+3][fm] = a4.w;
        }
        // B: state rows, natural [k][d]
        {
            const float* rr = &sre[(size_t)(k0+bk)*Ddim + d0 + cs];
            const float* ri = &sim[(size_t)(k0+bk)*Ddim + d0 + cs];
            *reinterpret_cast<float4*>(&Bre[bk][cs])   = *reinterpret_cast<const float4*>(rr);
            *reinterpret_cast<float4*>(&Bre[bk][cs+4]) = *reinterpret_cast<const float4*>(rr+4);
            *reinterpret_cast<float4*>(&Bim[bk][cs])   = *reinterpret_cast<const float4*>(ri);
            *reinterpret_cast<float4*>(&Bim[bk][cs+4]) = *reinterpret_cast<const float4*>(ri+4);
        }
        __syncthreads();
        #pragma unroll 4
        for (int kk = 0; kk < 16; kk++) {
            ull a2[4];
            #pragma unroll
            for (int i = 0; i < 4; i++) a2[i] = dup2(At[kk][ty*4+i]);
            #pragma unroll
            for (int q = 0; q < 4; q++) {
                ull brd = ldp(&Bre[kk][8*tx + 2*q]);
                ull bid = ldp(&Bim[kk][8*tx + 2*q]);
                #pragma unroll
                for (int i = 0; i < 4; i++) {
                    fma2(ar[i][q], a2[i], brd);
                    fma2(ai[i][q], a2[i], bid);
                }
            }
        }
        __syncthreads();
    }
    // epilogue: u = state + e^{iv} * acc
    const int db = d0 + 8*tx;
    float cvv[8], svv[8];
    #pragma unroll
    for (int e = 0; e < 8; e++) { cvv[e] = g_cv[db+e]; svv[e] = g_sv[db+e]; }
    #pragma unroll
    for (int i = 0; i < 4; i++) {
        int p = p0 + ty*4 + i;
        const float* prr = &sre[(size_t)p * Ddim + db];
        const float* pri = &sim[(size_t)p * Ddim + db];
        float s_r[8], s_i[8];
        *reinterpret_cast<float4*>(&s_r[0]) = *reinterpret_cast<const float4*>(prr);
        *reinterpret_cast<float4*>(&s_r[4]) = *reinterpret_cast<const float4*>(prr+4);
        *reinterpret_cast<float4*>(&s_i[0]) = *reinterpret_cast<const float4*>(pri);
        *reinterpret_cast<float4*>(&s_i[4]) = *reinterpret_cast<const float4*>(pri+4);
        float o_r[8], o_i[8];
        #pragma unroll
        for (int q = 0; q < 4; q++) {
            float2 tr = up(ar[i][q]);
            float2 ti = up(ai[i][q]);
            o_r[2*q]   = s_r[2*q]   + cvv[2*q]   * tr.x - svv[2*q]   * ti.x;
            o_i[2*q]   = s_i[2*q]   + svv[2*q]   * tr.x + cvv[2*q]   * ti.x;
            o_r[2*q+1] = s_r[2*q+1] + cvv[2*q+1] * tr.y - svv[2*q+1] * ti.y;
            o_i[2*q+1] = s_i[2*q+1] + svv[2*q+1] * tr.y + cvv[2*q+1] * ti.y;
        }
        size_t ob = (size_t)b * Pdim * Ddim + (size_t)p * Ddim + db;
        *reinterpret_cast<float4*>(&g_u_re[ob])   = *reinterpret_cast<float4*>(&o_r[0]);
        *reinterpret_cast<float4*>(&g_u_re[ob+4]) = *reinterpret_cast<float4*>(&o_r[4]);
        *reinterpret_cast<float4*>(&g_u_im[ob])   = *reinterpret_cast<float4*>(&o_i[0]);
        *reinterpret_cast<float4*>(&g_u_im[ob+4]) = *reinterpret_cast<float4*>(&o_i[4]);
    }
}

// ---------------------------------------------------------------- new = u @ (ffr + i*ffi) (FFMA2, n-pairs)
// tile: 64 m-rows x 128 n-cols, K=512
__global__ void __launch_bounds__(256, 2) k_ff(const float* __restrict__ ffr,
                                               const float* __restrict__ ffi) {
    __shared__ float Aur[16][66], Aui[16][66];
    __shared__ float Bfr[16][132], Bfi[16][132];
    const int tid = threadIdx.x;
    const int tx = tid & 15, ty = tid >> 4;
    const int m0 = blockIdx.y * 64, n0 = blockIdx.x * 128;
    float* __restrict__ nre = g_cur ? g_re0 : g_re1;
    float* __restrict__ nim = g_cur ? g_im0 : g_im1;

    ull cr[4][4], ci[4][4];
    #pragma unroll
    for (int i = 0; i < 4; i++)
        #pragma unroll
        for (int q = 0; q < 4; q++) { cr[i][q] = 0ULL; ci[i][q] = 0ULL; }

    const int fm = tid >> 2;
    const int kc = (tid & 3) * 4;
    const int bk = tid >> 4;
    const int cs = (tid & 15) * 8;

    for (int k0 = 0; k0 < Ddim; k0 += 16) {
        // A: u transposed [k][m]
        {
            float4 r4 = *reinterpret_cast<const float4*>(&g_u_re[(size_t)(m0+fm)*Ddim + k0 + kc]);
            float4 i4 = *reinterpret_cast<const float4*>(&g_u_im[(size_t)(m0+fm)*Ddim + k0 + kc]);
            Aur[kc+0][fm] = r4.x; Aur[kc+1][fm] = r4.y; Aur[kc+2][fm] = r4.z; Aur[kc+3][fm] = r4.w;
            Aui[kc+0][fm] = i4.x; Aui[kc+1][fm] = i4.y; Aui[kc+2][fm] = i4.z; Aui[kc+3][fm] = i4.w;
        }
        // B: ff rows, natural [k][n]
        {
            const float* rr = &ffr[(size_t)(k0+bk)*Ddim + n0 + cs];
            const float* ri = &ffi[(size_t)(k0+bk)*Ddim + n0 + cs];
            *reinterpret_cast<float4*>(&Bfr[bk][cs])   = *reinterpret_cast<const float4*>(rr);
            *reinterpret_cast<float4*>(&Bfr[bk][cs+4]) = *reinterpret_cast<const float4*>(rr+4);
            *reinterpret_cast<float4*>(&Bfi[bk][cs])   = *reinterpret_cast<const float4*>(ri);
            *reinterpret_cast<float4*>(&Bfi[bk][cs+4]) = *reinterpret_cast<const float4*>(ri+4);
        }
        __syncthreads();
        #pragma unroll 4
        for (int kk = 0; kk < 16; kk++) {
            ull ur2[4], ui2[4], nui2[4];
            #pragma unroll
            for (int i = 0; i < 4; i++) {
                float urv = Aur[kk][ty*4+i];
                float uiv = Aui[kk][ty*4+i];
                ur2[i]  = dup2(urv);
                ui2[i]  = dup2(uiv);
                nui2[i] = dup2(-uiv);
            }
            #pragma unroll
            for (int q = 0; q < 4; q++) {
                ull brd = ldp(&Bfr[kk][8*tx + 2*q]);
                ull bid = ldp(&Bfi[kk][8*tx + 2*q]);
                #pragma unroll
                for (int i = 0; i < 4; i++) {
                    fma2(cr[i][q], ur2[i],  brd);
                    fma2(cr[i][q], nui2[i], bid);
                    fma2(ci[i][q], ur2[i],  bid);
                    fma2(ci[i][q], ui2[i],  brd);
                }
            }
        }
        __syncthreads();
    }
    const int nb = n0 + 8*tx;
    #pragma unroll
    for (int i = 0; i < 4; i++) {
        int m = m0 + ty*4 + i;
        float o_r[8], o_i[8];
        #pragma unroll
        for (int q = 0; q < 4; q++) {
            float2 vr = up(cr[i][q]);
            float2 vi = up(ci[i][q]);
            o_r[2*q] = vr.x; o_r[2*q+1] = vr.y;
            o_i[2*q] = vi.x; o_i[2*q+1] = vi.y;
        }
        size_t ob = (size_t)m * Ddim + nb;
        *reinterpret_cast<float4*>(&nre[ob])   = *reinterpret_cast<float4*>(&o_r[0]);
        *reinterpret_cast<float4*>(&nre[ob+4]) = *reinterpret_cast<float4*>(&o_r[4]);
        *reinterpret_cast<float4*>(&nim[ob])   = *reinterpret_cast<float4*>(&o_i[0]);
        *reinterpret_cast<float4*>(&nim[ob+4]) = *reinterpret_cast<float4*>(&o_i[4]);
    }
}

// ---------------------------------------------------------------- complex_norm over rows of length D
__global__ void k_norm() {
    float* nre = g_cur ? g_re0 : g_re1;
    float* nim = g_cur ? g_im0 : g_im1;
    const int row = blockIdx.x;
    const int tid = threadIdx.x;
    const size_t base = (size_t)row * Ddim;
    float r0 = nre[base + tid],       i0 = nim[base + tid];
    float r1 = nre[base + tid + 256], i1 = nim[base + tid + 256];
    float m0 = sqrtf(r0*r0 + i0*i0);
    float m1 = sqrtf(r1*r1 + i1*i1);
    __shared__ float s_sum[256], s_sq[256];
    s_sum[tid] = m0 + m1;
    s_sq[tid]  = m0*m0 + m1*m1;
    __syncthreads();
    for (int s = 128; s > 0; s >>= 1) {
        if (tid < s) { s_sum[tid] += s_sum[tid+s]; s_sq[tid] += s_sq[tid+s]; }
        __syncthreads();
    }
    float mean = s_sum[0] * (1.0f / 512.0f);
    float var  = (s_sq[0] - 512.0f * mean * mean) * (1.0f / 511.0f);
    var = fmaxf(var, 0.0f);
    float inv = 1.0f / (sqrtf(var) + 1e-5f);
    float sc0 = tanhf((m0 - mean) * inv) / (m0 + 1e-5f);
    float sc1 = tanhf((m1 - mean) * inv) / (m1 + 1e-5f);
    nre[base + tid]       = r0 * sc0;
    nim[base + tid]       = i0 * sc0;
    nre[base + tid + 256] = r1 * sc1;
    nim[base + tid + 256] = i1 * sc1;
}

// ---------------------------------------------------------------- diff partials (deterministic)
__global__ void k_diff() {
    const float* nre = g_cur ? g_re0 : g_re1;
    const float* nim = g_cur ? g_im0 : g_im1;
    const float* pre = g_cur ? g_re1 : g_re0;
    const float* pim = g_cur ? g_im1 : g_im0;
    const int tid = threadIdx.x;
    const size_t start = (size_t)blockIdx.x * 256 + tid;
    double ld = 0.0, lnn = 0.0;
    #pragma unroll
    for (int i = 0; i < 16; i++) {
        size_t idx = start + (size_t)i * (NPART * 256);
        float nr = nre[idx], ni = nim[idx];
        float dr = nr - pre[idx], di = ni - pim[idx];
        ld  += (double)dr * dr + (double)di * di;
        lnn += (double)nr * nr + (double)ni * ni;
    }
    __shared__ double sd[256], sn[256];
    sd[tid] = ld; sn[tid] = lnn;
    __syncthreads();
    for (int s = 128; s > 0; s >>= 1) {
        if (tid < s) { sd[tid] += sd[tid+s]; sn[tid] += sn[tid+s]; }
        __syncthreads();
    }
    if (tid == 0) { g_part_d[blockIdx.x] = sd[0]; g_part_n[blockIdx.x] = sn[0]; }
}

__global__ void k_flag() {
    const int tid = threadIdx.x;
    double ld = 0.0, lnn = 0.0;
    for (int i = tid; i < NPART; i += 256) { ld += g_part_d[i]; lnn += g_part_n[i]; }
    __shared__ double sd[256], sn[256];
    sd[tid] = ld; sn[tid] = lnn;
    __syncthreads();
    for (int s = 128; s > 0; s >>= 1) {
        if (tid < s) { sd[tid] += sd[tid+s]; sn[tid] += sn[tid+s]; }
        __syncthreads();
    }
    if (tid == 0) {
        float diff = (float)(sqrt(sd[0]) / (sqrt(sn[0]) + 1e-8));
        if (g_active) g_cur ^= 1;            // commit = buffer swap (uses pre-update active)
        if (diff < 1e-3f) g_active = 0;
    }
}

// ---------------------------------------------------------------- mean pool over P
__global__ void k_pool() {
    const float* sre = g_cur ? g_re1 : g_re0;
    const float* sim = g_cur ? g_im1 : g_im0;
    const int idx = blockIdx.x * 256 + threadIdx.x;   // b*D + d
    const int b = idx >> 9, d = idx & (Ddim - 1);
    const size_t base = (size_t)b * Pdim * Ddim + d;
    float accr = 0.0f, acci = 0.0f;
    for (int p = 0; p < Pdim; p++) {
        accr += sre[base + (size_t)p * Ddim];
        acci += sim[base + (size_t)p * Ddim];
    }
    g_pool_re[idx] = accr * (1.0f / 256.0f);
    g_pool_im[idx] = acci * (1.0f / 256.0f);
}

// ---------------------------------------------------------------- logits
__global__ void k_logits(float* __restrict__ out, const float* __restrict__ Wr,
                         const float* __restrict__ br, const float* __restrict__ Wi,
                         const float* __restrict__ bi) {
    const int b = blockIdx.x, tid = threadIdx.x;
    float pr0 = g_pool_re[b * Ddim + tid],       pi0 = g_pool_im[b * Ddim + tid];
    float pr1 = g_pool_re[b * Ddim + tid + 256], pi1 = g_pool_im[b * Ddim + tid + 256];
    __shared__ float red[256];
    for (int c = 0; c < Cdim; c++) {
        float v = pr0 * Wr[c * Ddim + tid] + pr1 * Wr[c * Ddim + tid + 256]
                + pi0 * Wi[c * Ddim + tid] + pi1 * Wi[c * Ddim + tid + 256];
        red[tid] = v;
        __syncthreads();
        for (int s = 128; s > 0; s >>= 1) {
            if (tid < s) red[tid] += red[tid+s];
            __syncthreads();
        }
        if (tid == 0) out[b * Cdim + c] = red[0] + br[c] + bi[c];
        __syncthreads();
    }
}

// ---------------------------------------------------------------- launch
extern "C" void kernel_launch(void* const* d_in, const int* in_sizes, int n_in,
                              void* d_out, int out_size) {
    const float* x   = (const float*)d_in[0];
    const float* Wp  = (const float*)d_in[1];
    const float* bp  = (const float*)d_in[2];
    const float* qr  = (const float*)d_in[3];
    const float* kr  = (const float*)d_in[4];
    const float* vr  = (const float*)d_in[5];
    const float* ffr = (const float*)d_in[6];
    const float* ffi = (const float*)d_in[7];
    const float* Wr  = (const float*)d_in[8];
    const float* br  = (const float*)d_in[9];
    const float* Wi  = (const float*)d_in[10];
    const float* bi  = (const float*)d_in[11];
    float* out = (float*)d_out;

    k_prep<<<1, 512>>>(qr, kr, vr);
    k_proj<<<dim3(Ddim/64, (Bdim*Pdim)/64), 256>>>(x, Wp, bp);
    for (int step = 0; step < 4; step++) {
        k_qk<<<dim3(1, Pdim/64, Bdim), 256>>>();
        k_softmax<<<Bdim*Pdim, 256>>>();
        k_av<<<dim3(Ddim/128, Pdim/64, Bdim), 256>>>();
        k_ff<<<dim3(Ddim/128, (Bdim*Pdim)/64), 256>>>(ffr, ffi);
        k_norm<<<Bdim*Pdim, 256>>>();
        k_diff<<<NPART, 256>>>();
        k_flag<<<1, 256>>>();
    }
    k_pool<<<(Bdim*Ddim)/256, 256>>>();
    k_logits<<<Bdim, 256>>>(out, Wr, br, Wi, bi);
}

// round 11
// speedup vs baseline: 1.3481x; 1.3481x over previous
#include <cuda_runtime.h>
#include <math.h>

#define Bdim 128
#define Pdim 256
#define PIXdim 256
#define Ddim 512
#define Cdim 10

#define NSTATE (Bdim*Pdim*Ddim)   // 16,777,216
#define NATTN  (Bdim*Pdim*Pdim)   // 8,388,608
#define NROWS  (Bdim*Pdim)        // 32768

static __device__ float g_re0[NSTATE];
static __device__ float g_im0[NSTATE];
static __device__ float g_re1[NSTATE];
static __device__ float g_im1[NSTATE];
static __device__ float g_u_re[NSTATE];
static __device__ float g_u_im[NSTATE];
static __device__ float g_attn[NATTN];
static __device__ float g_pool_re[Bdim*Ddim];
static __device__ float g_pool_im[Bdim*Ddim];
static __device__ float g_cd[Ddim], g_sd[Ddim], g_cv[Ddim], g_sv[Ddim];
static __device__ double g_part_d[NROWS];
static __device__ double g_part_n[NROWS];
static __device__ int g_active;
static __device__ int g_cur;

// ---------------------------------------------------------------- prep
__global__ void k_prep(const float* __restrict__ qr, const float* __restrict__ kr,
                       const float* __restrict__ vr) {
    int d = threadIdx.x;
    if (d < Ddim) {
        float cq, sq, ck, sk, cv, sv;
        sincosf(qr[d], &sq, &cq);
        sincosf(kr[d], &sk, &ck);
        sincosf(vr[d], &sv, &cv);
        g_cd[d] = cq*ck + sq*sk;
        g_sd[d] = sq*ck - cq*sk;
        g_cv[d] = cv;
        g_sv[d] = sv;
    }
    if (d == 0) { g_active = 1; g_cur = 0; }
}

// ---------------------------------------------------------------- proj: state = tanh(x@Wp^T+bp) * e^{i phase}
__global__ void k_proj(const float* __restrict__ x, const float* __restrict__ Wp,
                       const float* __restrict__ bp) {
    __shared__ float As[16][68];
    __shared__ float Bs[16][68];
    const int tid = threadIdx.x;
    const int m0 = blockIdx.y * 64, n0 = blockIdx.x * 64;
    const int tm = (tid >> 4) * 4, tn = (tid & 15) * 4;
    const int lk = tid & 15, lr = tid >> 4;
    float acc[4][4] = {};
    for (int k0 = 0; k0 < PIXdim; k0 += 16) {
        #pragma unroll
        for (int i = 0; i < 4; i++) {
            As[lk][lr + 16*i] = x [(size_t)(m0 + lr + 16*i) * PIXdim + (k0 + lk)];
            Bs[lk][lr + 16*i] = Wp[(size_t)(n0 + lr + 16*i) * PIXdim + (k0 + lk)];
        }
        __syncthreads();
        #pragma unroll
        for (int kk = 0; kk < 16; kk++) {
            float a[4], b[4];
            #pragma unroll
            for (int i = 0; i < 4; i++) { a[i] = As[kk][tm+i]; b[i] = Bs[kk][tn+i]; }
            #pragma unroll
            for (int i = 0; i < 4; i++)
                #pragma unroll
                for (int j = 0; j < 4; j++)
                    acc[i][j] = fmaf(a[i], b[j], acc[i][j]);
        }
        __syncthreads();
    }
    const float PI = 3.14159265358979323846f;
    #pragma unroll
    for (int j = 0; j < 4; j++) {
        int n = n0 + tn + j;
        float freq = 1.0f / powf(10000.0f, (float)n / (float)Ddim);
        float bpv = bp[n];
        #pragma unroll
        for (int i = 0; i < 4; i++) {
            int m = m0 + tm + i;
            int p = m & (Pdim - 1);
            float t = tanhf(acc[i][j] + bpv);
            float ph = ((float)p * freq) * PI;
            float s, c;
            sincosf(ph, &s, &c);
            size_t idx = (size_t)m * Ddim + n;
            g_re0[idx] = t * c;
            g_im0[idx] = t * s;
        }
    }
}

// ---------------------------------------------------------------- QK^H real part * scale (R1 core verbatim)
__global__ void k_qk() {
    __shared__ float Ar[16][68], Ai[16][68], Br[16][68], Bi[16][68];
    const int tid = threadIdx.x;
    const int b = blockIdx.z;
    const int p0 = blockIdx.y * 64, q0 = blockIdx.x * 64;
    const int tm = (tid >> 4) * 4, tn = (tid & 15) * 4;
    const int lk = tid & 15, lr = tid >> 4;
    const float* __restrict__ sre = (g_cur ? g_re1 : g_re0) + (size_t)b * Pdim * Ddim;
    const float* __restrict__ sim = (g_cur ? g_im1 : g_im0) + (size_t)b * Pdim * Ddim;
    float acc[4][4] = {};
    for (int k0 = 0; k0 < Ddim; k0 += 16) {
        int d = k0 + lk;
        float cd = g_cd[d], sd = g_sd[d];
        #pragma unroll
        for (int i = 0; i < 4; i++) {
            int pr = p0 + lr + 16*i;
            float re = sre[(size_t)pr * Ddim + d];
            float im = sim[(size_t)pr * Ddim + d];
            Ar[lk][lr + 16*i] = re * cd - im * sd;
            Ai[lk][lr + 16*i] = re * sd + im * cd;
            int qq = q0 + lr + 16*i;
            Br[lk][lr + 16*i] = sre[(size_t)qq * Ddim + d];
            Bi[lk][lr + 16*i] = sim[(size_t)qq * Ddim + d];
        }
        __syncthreads();
        #pragma unroll
        for (int kk = 0; kk < 16; kk++) {
            float ar[4], ai[4], br[4], bi[4];
            #pragma unroll
            for (int i = 0; i < 4; i++) {
                ar[i] = Ar[kk][tm+i]; ai[i] = Ai[kk][tm+i];
                br[i] = Br[kk][tn+i]; bi[i] = Bi[kk][tn+i];
            }
            #pragma unroll
            for (int i = 0; i < 4; i++)
                #pragma unroll
                for (int j = 0; j < 4; j++) {
                    acc[i][j] = fmaf(ar[i], br[j], acc[i][j]);
                    acc[i][j] = fmaf(ai[i], bi[j], acc[i][j]);
                }
        }
        __syncthreads();
    }
    const float SCALE = 0.3535533905932738f;  // 8/sqrt(512)
    float* out = g_attn + (size_t)b * Pdim * Pdim;
    #pragma unroll
    for (int i = 0; i < 4; i++)
        #pragma unroll
        for (int j = 0; j < 4; j++)
            out[(size_t)(p0 + tm + i) * Pdim + (q0 + tn + j)] = acc[i][j] * SCALE;
}

// ---------------------------------------------------------------- softmax (R1 pairing, shuffle tail)
__global__ void k_softmax() {
    const int row = blockIdx.x;
    const int tid = threadIdx.x;
    float* a = g_attn + (size_t)row * Pdim;
    float v = a[tid];
    __shared__ float red[256];
    __shared__ float bc;
    red[tid] = v;
    __syncthreads();
    if (tid < 128) red[tid] = fmaxf(red[tid], red[tid + 128]);
    __syncthreads();
    if (tid < 64) red[tid] = fmaxf(red[tid], red[tid + 64]);
    __syncthreads();
    if (tid < 32) {
        float m = fmaxf(red[tid], red[tid + 32]);
        #pragma unroll
        for (int s = 16; s > 0; s >>= 1)
            m = fmaxf(m, __shfl_down_sync(0xffffffffu, m, s));
        if (tid == 0) bc = m;
    }
    __syncthreads();
    float mx = bc;
    float e = expf(v - mx);
    red[tid] = e;
    __syncthreads();
    if (tid < 128) red[tid] += red[tid + 128];
    __syncthreads();
    if (tid < 64) red[tid] += red[tid + 64];
    __syncthreads();
    if (tid < 32) {
        float s0 = red[tid] + red[tid + 32];
        #pragma unroll
        for (int s = 16; s > 0; s >>= 1)
            s0 += __shfl_down_sync(0xffffffffu, s0, s);
        if (tid == 0) bc = s0;
    }
    __syncthreads();
    a[tid] = e / bc;
}

// ---------------------------------------------------------------- u = prev + e^{iv} * (attn @ state) (R1 core verbatim)
__global__ void k_av() {
    __shared__ float As[16][68];
    __shared__ float Br[16][64], Bi[16][64];
    const int tid = threadIdx.x;
    const int b = blockIdx.z;
    const int p0 = blockIdx.y * 64, n0 = blockIdx.x * 64;
    const int tm = (tid >> 4) * 4, tn = (tid & 15) * 4;
    const int lk = tid & 15, lr = tid >> 4;
    const int ln = tid & 63, lkb = tid >> 6;
    const float* __restrict__ sre = (g_cur ? g_re1 : g_re0) + (size_t)b * Pdim * Ddim;
    const float* __restrict__ sim = (g_cur ? g_im1 : g_im0) + (size_t)b * Pdim * Ddim;
    const float* __restrict__ at  = g_attn + (size_t)b * Pdim * Pdim;
    float ar[4][4] = {}, ai[4][4] = {};
    for (int k0 = 0; k0 < Pdim; k0 += 16) {
        #pragma unroll
        for (int i = 0; i < 4; i++)
            As[lk][lr + 16*i] = at[(size_t)(p0 + lr + 16*i) * Pdim + (k0 + lk)];
        #pragma unroll
        for (int i = 0; i < 4; i++) {
            int kq = k0 + lkb * 4 + i;
            Br[lkb*4 + i][ln] = sre[(size_t)kq * Ddim + n0 + ln];
            Bi[lkb*4 + i][ln] = sim[(size_t)kq * Ddim + n0 + ln];
        }
        __syncthreads();
        #pragma unroll
        for (int kk = 0; kk < 16; kk++) {
            float a[4], br[4], bi[4];
            #pragma unroll
            for (int i = 0; i < 4; i++) {
                a[i]  = As[kk][tm+i];
                br[i] = Br[kk][tn+i];
                bi[i] = Bi[kk][tn+i];
            }
            #pragma unroll
            for (int i = 0; i < 4; i++)
                #pragma unroll
                for (int j = 0; j < 4; j++) {
                    ar[i][j] = fmaf(a[i], br[j], ar[i][j]);
                    ai[i][j] = fmaf(a[i], bi[j], ai[i][j]);
                }
        }
        __syncthreads();
    }
    #pragma unroll
    for (int j = 0; j < 4; j++) {
        int d = n0 + tn + j;
        float cv = g_cv[d], sv = g_sv[d];
        #pragma unroll
        for (int i = 0; i < 4; i++) {
            int p = p0 + tm + i;
            size_t idx = (size_t)b * Pdim * Ddim + (size_t)p * Ddim + d;
            float tr = ar[i][j], ti = ai[i][j];
            g_u_re[idx] = sre[(size_t)p * Ddim + d] + cv * tr - sv * ti;
            g_u_im[idx] = sim[(size_t)p * Ddim + d] + sv * tr + cv * ti;
        }
    }
}

// ---------------------------------------------------------------- new = u @ (ffr + i*ffi) (R1 core verbatim)
__global__ void k_ff(const float* __restrict__ ffr, const float* __restrict__ ffi) {
    __shared__ float Aur[16][68], Aui[16][68];
    __shared__ float Bfr[16][64], Bfi[16][64];
    const int tid = threadIdx.x;
    const int m0 = blockIdx.y * 64, n0 = blockIdx.x * 64;
    const int tm = (tid >> 4) * 4, tn = (tid & 15) * 4;
    const int lk = tid & 15, lr = tid >> 4;
    const int ln = tid & 63, lkb = tid >> 6;
    float* __restrict__ nre = g_cur ? g_re0 : g_re1;
    float* __restrict__ nim = g_cur ? g_im0 : g_im1;
    float cr[4][4] = {}, ci[4][4] = {};
    for (int k0 = 0; k0 < Ddim; k0 += 16) {
        #pragma unroll
        for (int i = 0; i < 4; i++) {
            size_t ga = (size_t)(m0 + lr + 16*i) * Ddim + (k0 + lk);
            Aur[lk][lr + 16*i] = g_u_re[ga];
            Aui[lk][lr + 16*i] = g_u_im[ga];
        }
        #pragma unroll
        for (int i = 0; i < 4; i++) {
            int kd = k0 + lkb * 4 + i;
            Bfr[lkb*4 + i][ln] = ffr[(size_t)kd * Ddim + n0 + ln];
            Bfi[lkb*4 + i][ln] = ffi[(size_t)kd * Ddim + n0 + ln];
        }
        __syncthreads();
        #pragma unroll
        for (int kk = 0; kk < 16; kk++) {
            float ur[4], ui[4], fr[4], fi[4];
            #pragma unroll
            for (int i = 0; i < 4; i++) {
                ur[i] = Aur[kk][tm+i]; ui[i] = Aui[kk][tm+i];
                fr[i] = Bfr[kk][tn+i]; fi[i] = Bfi[kk][tn+i];
            }
            #pragma unroll
            for (int i = 0; i < 4; i++)
                #pragma unroll
                for (int j = 0; j < 4; j++) {
                    cr[i][j] = fmaf(ur[i],  fr[j], cr[i][j]);
                    cr[i][j] = fmaf(-ui[i], fi[j], cr[i][j]);
                    ci[i][j] = fmaf(ur[i],  fi[j], ci[i][j]);
                    ci[i][j] = fmaf(ui[i],  fr[j], ci[i][j]);
                }
        }
        __syncthreads();
    }
    #pragma unroll
    for (int i = 0; i < 4; i++)
        #pragma unroll
        for (int j = 0; j < 4; j++) {
            size_t idx = (size_t)(m0 + tm + i) * Ddim + (n0 + tn + j);
            nre[idx] = cr[i][j];
            nim[idx] = ci[i][j];
        }
}

// ---------------------------------------------------------------- complex_norm (R1 expressions) + fused diff partials
__global__ void k_norm() {
    float* nre = g_cur ? g_re0 : g_re1;
    float* nim = g_cur ? g_im0 : g_im1;
    const float* pre = g_cur ? g_re1 : g_re0;
    const float* pim = g_cur ? g_im1 : g_im0;
    const int row = blockIdx.x;
    const int tid = threadIdx.x;
    const size_t base = (size_t)row * Ddim;
    float r0 = nre[base + tid],       i0 = nim[base + tid];
    float r1 = nre[base + tid + 256], i1 = nim[base + tid + 256];
    float m0 = sqrtf(r0*r0 + i0*i0);
    float m1 = sqrtf(r1*r1 + i1*i1);
    __shared__ float s_sum[256], s_sq[256];
    s_sum[tid] = m0 + m1;
    s_sq[tid]  = m0*m0 + m1*m1;
    __syncthreads();
    for (int s = 128; s > 0; s >>= 1) {
        if (tid < s) { s_sum[tid] += s_sum[tid+s]; s_sq[tid] += s_sq[tid+s]; }
        __syncthreads();
    }
    float mean = s_sum[0] * (1.0f / 512.0f);
    float var  = (s_sq[0] - 512.0f * mean * mean) * (1.0f / 511.0f);
    var = fmaxf(var, 0.0f);
    float inv = 1.0f / (sqrtf(var) + 1e-5f);
    float sc0 = tanhf((m0 - mean) * inv) / (m0 + 1e-5f);
    float sc1 = tanhf((m1 - mean) * inv) / (m1 + 1e-5f);
    float nr0 = r0 * sc0, ni0 = i0 * sc0;
    float nr1 = r1 * sc1, ni1 = i1 * sc1;
    nre[base + tid]       = nr0;
    nim[base + tid]       = ni0;
    nre[base + tid + 256] = nr1;
    nim[base + tid + 256] = ni1;
    // ---- fused diff partials (double; gates the swap only)
    __shared__ double sd[256], sn[256];
    float pr0 = pre[base + tid],       qi0 = pim[base + tid];
    float pr1 = pre[base + tid + 256], qi1 = pim[base + tid + 256];
    float dr0 = nr0 - pr0, di0 = ni0 - qi0;
    float dr1 = nr1 - pr1, di1 = ni1 - qi1;
    sd[tid] = (double)dr0*dr0 + (double)di0*di0 + (double)dr1*dr1 + (double)di1*di1;
    sn[tid] = (double)nr0*nr0 + (double)ni0*ni0 + (double)nr1*nr1 + (double)ni1*ni1;
    __syncthreads();
    for (int s = 128; s > 0; s >>= 1) {
        if (tid < s) { sd[tid] += sd[tid+s]; sn[tid] += sn[tid+s]; }
        __syncthreads();
    }
    if (tid == 0) { g_part_d[row] = sd[0]; g_part_n[row] = sn[0]; }
}

// ---------------------------------------------------------------- flag: reduce partials, swap buffers
__global__ void k_flag() {
    const int tid = threadIdx.x;
    double ld = 0.0, lnn = 0.0;
    for (int i = tid; i < NROWS; i += 256) { ld += g_part_d[i]; lnn += g_part_n[i]; }
    __shared__ double sd[256], sn[256];
    sd[tid] = ld; sn[tid] = lnn;
    __syncthreads();
    for (int s = 128; s > 0; s >>= 1) {
        if (tid < s) { sd[tid] += sd[tid+s]; sn[tid] += sn[tid+s]; }
        __syncthreads();
    }
    if (tid == 0) {
        float diff = (float)(sqrt(sd[0]) / (sqrt(sn[0]) + 1e-8));
        if (g_active) g_cur ^= 1;            // commit = buffer swap (uses pre-update active)
        if (diff < 1e-3f) g_active = 0;
    }
}

// ---------------------------------------------------------------- mean pool over P
__global__ void k_pool() {
    const float* sre = g_cur ? g_re1 : g_re0;
    const float* sim = g_cur ? g_im1 : g_im0;
    const int idx = blockIdx.x * 256 + threadIdx.x;   // b*D + d
    const int b = idx >> 9, d = idx & (Ddim - 1);
    const size_t base = (size_t)b * Pdim * Ddim + d;
    float accr = 0.0f, acci = 0.0f;
    for (int p = 0; p < Pdim; p++) {
        accr += sre[base + (size_t)p * Ddim];
        acci += sim[base + (size_t)p * Ddim];
    }
    g_pool_re[idx] = accr * (1.0f / 256.0f);
    g_pool_im[idx] = acci * (1.0f / 256.0f);
}

// ---------------------------------------------------------------- logits
__global__ void k_logits(float* __restrict__ out, const float* __restrict__ Wr,
                         const float* __restrict__ br, const float* __restrict__ Wi,
                         const float* __restrict__ bi) {
    const int b = blockIdx.x, tid = threadIdx.x;
    float pr0 = g_pool_re[b * Ddim + tid],       pi0 = g_pool_im[b * Ddim + tid];
    float pr1 = g_pool_re[b * Ddim + tid + 256], pi1 = g_pool_im[b * Ddim + tid + 256];
    __shared__ float red[256];
    for (int c = 0; c < Cdim; c++) {
        float v = pr0 * Wr[c * Ddim + tid] + pr1 * Wr[c * Ddim + tid + 256]
                + pi0 * Wi[c * Ddim + tid] + pi1 * Wi[c * Ddim + tid + 256];
        red[tid] = v;
        __syncthreads();
        for (int s = 128; s > 0; s >>= 1) {
            if (tid < s) red[tid] += red[tid+s];
            __syncthreads();
        }
        if (tid == 0) out[b * Cdim + c] = red[0] + br[c] + bi[c];
        __syncthreads();
    }
}

// ---------------------------------------------------------------- launch
extern "C" void kernel_launch(void* const* d_in, const int* in_sizes, int n_in,
                              void* d_out, int out_size) {
    const float* x   = (const float*)d_in[0];
    const float* Wp  = (const float*)d_in[1];
    const float* bp  = (const float*)d_in[2];
    const float* qr  = (const float*)d_in[3];
    const float* kr  = (const float*)d_in[4];
    const float* vr  = (const float*)d_in[5];
    const float* ffr = (const float*)d_in[6];
    const float* ffi = (const float*)d_in[7];
    const float* Wr  = (const float*)d_in[8];
    const float* br  = (const float*)d_in[9];
    const float* Wi  = (const float*)d_in[10];
    const float* bi  = (const float*)d_in[11];
    float* out = (float*)d_out;

    k_prep<<<1, 512>>>(qr, kr, vr);
    k_proj<<<dim3(Ddim/64, (Bdim*Pdim)/64), 256>>>(x, Wp, bp);
    for (int step = 0; step < 4; step++) {
        k_qk<<<dim3(Pdim/64, Pdim/64, Bdim), 256>>>();
        k_softmax<<<Bdim*Pdim, 256>>>();
        k_av<<<dim3(Ddim/64, Pdim/64, Bdim), 256>>>();
        k_ff<<<dim3(Ddim/64, (Bdim*Pdim)/64), 256>>>(ffr, ffi);
        k_norm<<<Bdim*Pdim, 256>>>();
        k_flag<<<1, 256>>>();
    }
    k_pool<<<(Bdim*Ddim)/256, 256>>>();
    k_logits<<<Bdim, 256>>>(out, Wr, br, Wi, bi);
}

// round 12
// speedup vs baseline: 1.3512x; 1.0023x over previous
#include <cuda_runtime.h>
#include <math.h>

#define Bdim 128
#define Pdim 256
#define PIXdim 256
#define Ddim 512
#define Cdim 10

#define NSTATE (Bdim*Pdim*Ddim)   // 16,777,216
#define NATTN  (Bdim*Pdim*Pdim)   // 8,388,608
#define NROWS  (Bdim*Pdim)        // 32768

static __device__ float g_re0[NSTATE];
static __device__ float g_im0[NSTATE];
static __device__ float g_re1[NSTATE];
static __device__ float g_im1[NSTATE];
static __device__ float g_u_re[NSTATE];
static __device__ float g_u_im[NSTATE];
static __device__ float g_attn[NATTN];
static __device__ float g_pool_re[Bdim*Ddim];
static __device__ float g_pool_im[Bdim*Ddim];
static __device__ float g_cd[Ddim], g_sd[Ddim], g_cv[Ddim], g_sv[Ddim];
static __device__ double g_part_d[NROWS];
static __device__ double g_part_n[NROWS];
static __device__ int g_active;
static __device__ int g_cur;

// ---------------------------------------------------------------- prep
__global__ void k_prep(const float* __restrict__ qr, const float* __restrict__ kr,
                       const float* __restrict__ vr) {
    int d = threadIdx.x;
    if (d < Ddim) {
        float cq, sq, ck, sk, cv, sv;
        sincosf(qr[d], &sq, &cq);
        sincosf(kr[d], &sk, &ck);
        sincosf(vr[d], &sv, &cv);
        g_cd[d] = cq*ck + sq*sk;
        g_sd[d] = sq*ck - cq*sk;
        g_cv[d] = cv;
        g_sv[d] = sv;
    }
    if (d == 0) { g_active = 1; g_cur = 0; }
}

// ---------------------------------------------------------------- proj: state = tanh(x@Wp^T+bp) * e^{i phase}
__global__ void k_proj(const float* __restrict__ x, const float* __restrict__ Wp,
                       const float* __restrict__ bp) {
    __shared__ float As[16][68];
    __shared__ float Bs[16][68];
    const int tid = threadIdx.x;
    const int m0 = blockIdx.y * 64, n0 = blockIdx.x * 64;
    const int tm = (tid >> 4) * 4, tn = (tid & 15) * 4;
    const int lk = tid & 15, lr = tid >> 4;
    float acc[4][4] = {};
    for (int k0 = 0; k0 < PIXdim; k0 += 16) {
        #pragma unroll
        for (int i = 0; i < 4; i++) {
            As[lk][lr + 16*i] = x [(size_t)(m0 + lr + 16*i) * PIXdim + (k0 + lk)];
            Bs[lk][lr + 16*i] = Wp[(size_t)(n0 + lr + 16*i) * PIXdim + (k0 + lk)];
        }
        __syncthreads();
        #pragma unroll
        for (int kk = 0; kk < 16; kk++) {
            float a[4], b[4];
            #pragma unroll
            for (int i = 0; i < 4; i++) { a[i] = As[kk][tm+i]; b[i] = Bs[kk][tn+i]; }
            #pragma unroll
            for (int i = 0; i < 4; i++)
                #pragma unroll
                for (int j = 0; j < 4; j++)
                    acc[i][j] = fmaf(a[i], b[j], acc[i][j]);
        }
        __syncthreads();
    }
    const float PI = 3.14159265358979323846f;
    #pragma unroll
    for (int j = 0; j < 4; j++) {
        int n = n0 + tn + j;
        float freq = 1.0f / powf(10000.0f, (float)n / (float)Ddim);
        float bpv = bp[n];
        #pragma unroll
        for (int i = 0; i < 4; i++) {
            int m = m0 + tm + i;
            int p = m & (Pdim - 1);
            float t = tanhf(acc[i][j] + bpv);
            float ph = ((float)p * freq) * PI;
            float s, c;
            sincosf(ph, &s, &c);
            size_t idx = (size_t)m * Ddim + n;
            g_re0[idx] = t * c;
            g_im0[idx] = t * s;
        }
    }
}

// ---------------------------------------------------------------- QK^H real part * scale (R1 core verbatim)
__global__ void k_qk() {
    if (!g_active) return;
    __shared__ float Ar[16][68], Ai[16][68], Br[16][68], Bi[16][68];
    const int tid = threadIdx.x;
    const int b = blockIdx.z;
    const int p0 = blockIdx.y * 64, q0 = blockIdx.x * 64;
    const int tm = (tid >> 4) * 4, tn = (tid & 15) * 4;
    const int lk = tid & 15, lr = tid >> 4;
    const float* __restrict__ sre = (g_cur ? g_re1 : g_re0) + (size_t)b * Pdim * Ddim;
    const float* __restrict__ sim = (g_cur ? g_im1 : g_im0) + (size_t)b * Pdim * Ddim;
    float acc[4][4] = {};
    for (int k0 = 0; k0 < Ddim; k0 += 16) {
        int d = k0 + lk;
        float cd = g_cd[d], sd = g_sd[d];
        #pragma unroll
        for (int i = 0; i < 4; i++) {
            int pr = p0 + lr + 16*i;
            float re = sre[(size_t)pr * Ddim + d];
            float im = sim[(size_t)pr * Ddim + d];
            Ar[lk][lr + 16*i] = re * cd - im * sd;
            Ai[lk][lr + 16*i] = re * sd + im * cd;
            int qq = q0 + lr + 16*i;
            Br[lk][lr + 16*i] = sre[(size_t)qq * Ddim + d];
            Bi[lk][lr + 16*i] = sim[(size_t)qq * Ddim + d];
        }
        __syncthreads();
        #pragma unroll
        for (int kk = 0; kk < 16; kk++) {
            float ar[4], ai[4], br[4], bi[4];
            #pragma unroll
            for (int i = 0; i < 4; i++) {
                ar[i] = Ar[kk][tm+i]; ai[i] = Ai[kk][tm+i];
                br[i] = Br[kk][tn+i]; bi[i] = Bi[kk][tn+i];
            }
            #pragma unroll
            for (int i = 0; i < 4; i++)
                #pragma unroll
                for (int j = 0; j < 4; j++) {
                    acc[i][j] = fmaf(ar[i], br[j], acc[i][j]);
                    acc[i][j] = fmaf(ai[i], bi[j], acc[i][j]);
                }
        }
        __syncthreads();
    }
    const float SCALE = 0.3535533905932738f;  // 8/sqrt(512)
    float* out = g_attn + (size_t)b * Pdim * Pdim;
    #pragma unroll
    for (int i = 0; i < 4; i++)
        #pragma unroll
        for (int j = 0; j < 4; j++)
            out[(size_t)(p0 + tm + i) * Pdim + (q0 + tn + j)] = acc[i][j] * SCALE;
}

// ---------------------------------------------------------------- softmax (R1 pairing, shuffle tail)
__global__ void k_softmax() {
    if (!g_active) return;
    const int row = blockIdx.x;
    const int tid = threadIdx.x;
    float* a = g_attn + (size_t)row * Pdim;
    float v = a[tid];
    __shared__ float red[256];
    __shared__ float bc;
    red[tid] = v;
    __syncthreads();
    if (tid < 128) red[tid] = fmaxf(red[tid], red[tid + 128]);
    __syncthreads();
    if (tid < 64) red[tid] = fmaxf(red[tid], red[tid + 64]);
    __syncthreads();
    if (tid < 32) {
        float m = fmaxf(red[tid], red[tid + 32]);
        #pragma unroll
        for (int s = 16; s > 0; s >>= 1)
            m = fmaxf(m, __shfl_down_sync(0xffffffffu, m, s));
        if (tid == 0) bc = m;
    }
    __syncthreads();
    float mx = bc;
    float e = expf(v - mx);
    red[tid] = e;
    __syncthreads();
    if (tid < 128) red[tid] += red[tid + 128];
    __syncthreads();
    if (tid < 64) red[tid] += red[tid + 64];
    __syncthreads();
    if (tid < 32) {
        float s0 = red[tid] + red[tid + 32];
        #pragma unroll
        for (int s = 16; s > 0; s >>= 1)
            s0 += __shfl_down_sync(0xffffffffu, s0, s);
        if (tid == 0) bc = s0;
    }
    __syncthreads();
    a[tid] = e / bc;
}

// ---------------------------------------------------------------- u = prev + e^{iv} * (attn @ state) (R1 core verbatim)
__global__ void k_av() {
    if (!g_active) return;
    __shared__ float As[16][68];
    __shared__ float Br[16][64], Bi[16][64];
    const int tid = threadIdx.x;
    const int b = blockIdx.z;
    const int p0 = blockIdx.y * 64, n0 = blockIdx.x * 64;
    const int tm = (tid >> 4) * 4, tn = (tid & 15) * 4;
    const int lk = tid & 15, lr = tid >> 4;
    const int ln = tid & 63, lkb = tid >> 6;
    const float* __restrict__ sre = (g_cur ? g_re1 : g_re0) + (size_t)b * Pdim * Ddim;
    const float* __restrict__ sim = (g_cur ? g_im1 : g_im0) + (size_t)b * Pdim * Ddim;
    const float* __restrict__ at  = g_attn + (size_t)b * Pdim * Pdim;
    float ar[4][4] = {}, ai[4][4] = {};
    for (int k0 = 0; k0 < Pdim; k0 += 16) {
        #pragma unroll
        for (int i = 0; i < 4; i++)
            As[lk][lr + 16*i] = at[(size_t)(p0 + lr + 16*i) * Pdim + (k0 + lk)];
        #pragma unroll
        for (int i = 0; i < 4; i++) {
            int kq = k0 + lkb * 4 + i;
            Br[lkb*4 + i][ln] = sre[(size_t)kq * Ddim + n0 + ln];
            Bi[lkb*4 + i][ln] = sim[(size_t)kq * Ddim + n0 + ln];
        }
        __syncthreads();
        #pragma unroll
        for (int kk = 0; kk < 16; kk++) {
            float a[4], br[4], bi[4];
            #pragma unroll
            for (int i = 0; i < 4; i++) {
                a[i]  = As[kk][tm+i];
                br[i] = Br[kk][tn+i];
                bi[i] = Bi[kk][tn+i];
            }
            #pragma unroll
            for (int i = 0; i < 4; i++)
                #pragma unroll
                for (int j = 0; j < 4; j++) {
                    ar[i][j] = fmaf(a[i], br[j], ar[i][j]);
                    ai[i][j] = fmaf(a[i], bi[j], ai[i][j]);
                }
        }
        __syncthreads();
    }
    #pragma unroll
    for (int j = 0; j < 4; j++) {
        int d = n0 + tn + j;
        float cv = g_cv[d], sv = g_sv[d];
        #pragma unroll
        for (int i = 0; i < 4; i++) {
            int p = p0 + tm + i;
            size_t idx = (size_t)b * Pdim * Ddim + (size_t)p * Ddim + d;
            float tr = ar[i][j], ti = ai[i][j];
            g_u_re[idx] = sre[(size_t)p * Ddim + d] + cv * tr - sv * ti;
            g_u_im[idx] = sim[(size_t)p * Ddim + d] + sv * tr + cv * ti;
        }
    }
}

// ---------------------------------------------------------------- new = u @ (ffr + i*ffi) (R1 core verbatim)
__global__ void k_ff(const float* __restrict__ ffr, const float* __restrict__ ffi) {
    if (!g_active) return;
    __shared__ float Aur[16][68], Aui[16][68];
    __shared__ float Bfr[16][64], Bfi[16][64];
    const int tid = threadIdx.x;
    const int m0 = blockIdx.y * 64, n0 = blockIdx.x * 64;
    const int tm = (tid >> 4) * 4, tn = (tid & 15) * 4;
    const int lk = tid & 15, lr = tid >> 4;
    const int ln = tid & 63, lkb = tid >> 6;
    float* __restrict__ nre = g_cur ? g_re0 : g_re1;
    float* __restrict__ nim = g_cur ? g_im0 : g_im1;
    float cr[4][4] = {}, ci[4][4] = {};
    for (int k0 = 0; k0 < Ddim; k0 += 16) {
        #pragma unroll
        for (int i = 0; i < 4; i++) {
            size_t ga = (size_t)(m0 + lr + 16*i) * Ddim + (k0 + lk);
            Aur[lk][lr + 16*i] = g_u_re[ga];
            Aui[lk][lr + 16*i] = g_u_im[ga];
        }
        #pragma unroll
        for (int i = 0; i < 4; i++) {
            int kd = k0 + lkb * 4 + i;
            Bfr[lkb*4 + i][ln] = ffr[(size_t)kd * Ddim + n0 + ln];
            Bfi[lkb*4 + i][ln] = ffi[(size_t)kd * Ddim + n0 + ln];
        }
        __syncthreads();
        #pragma unroll
        for (int kk = 0; kk < 16; kk++) {
            float ur[4], ui[4], fr[4], fi[4];
            #pragma unroll
            for (int i = 0; i < 4; i++) {
                ur[i] = Aur[kk][tm+i]; ui[i] = Aui[kk][tm+i];
                fr[i] = Bfr[kk][tn+i]; fi[i] = Bfi[kk][tn+i];
            }
            #pragma unroll
            for (int i = 0; i < 4; i++)
                #pragma unroll
                for (int j = 0; j < 4; j++) {
                    cr[i][j] = fmaf(ur[i],  fr[j], cr[i][j]);
                    cr[i][j] = fmaf(-ui[i], fi[j], cr[i][j]);
                    ci[i][j] = fmaf(ur[i],  fi[j], ci[i][j]);
                    ci[i][j] = fmaf(ui[i],  fr[j], ci[i][j]);
                }
        }
        __syncthreads();
    }
    #pragma unroll
    for (int i = 0; i < 4; i++)
        #pragma unroll
        for (int j = 0; j < 4; j++) {
            size_t idx = (size_t)(m0 + tm + i) * Ddim + (n0 + tn + j);
            nre[idx] = cr[i][j];
            nim[idx] = ci[i][j];
        }
}

// ---------------------------------------------------------------- complex_norm (R1 expressions) + fused diff partials
__global__ void k_norm() {
    if (!g_active) return;
    float* nre = g_cur ? g_re0 : g_re1;
    float* nim = g_cur ? g_im0 : g_im1;
    const float* pre = g_cur ? g_re1 : g_re0;
    const float* pim = g_cur ? g_im1 : g_im0;
    const int row = blockIdx.x;
    const int tid = threadIdx.x;
    const size_t base = (size_t)row * Ddim;
    float r0 = nre[base + tid],       i0 = nim[base + tid];
    float r1 = nre[base + tid + 256], i1 = nim[base + tid + 256];
    float m0 = sqrtf(r0*r0 + i0*i0);
    float m1 = sqrtf(r1*r1 + i1*i1);
    __shared__ float s_sum[256], s_sq[256];
    s_sum[tid] = m0 + m1;
    s_sq[tid]  = m0*m0 + m1*m1;
    __syncthreads();
    for (int s = 128; s > 0; s >>= 1) {
        if (tid < s) { s_sum[tid] += s_sum[tid+s]; s_sq[tid] += s_sq[tid+s]; }
        __syncthreads();
    }
    float mean = s_sum[0] * (1.0f / 512.0f);
    float var  = (s_sq[0] - 512.0f * mean * mean) * (1.0f / 511.0f);
    var = fmaxf(var, 0.0f);
    float inv = 1.0f / (sqrtf(var) + 1e-5f);
    float sc0 = tanhf((m0 - mean) * inv) / (m0 + 1e-5f);
    float sc1 = tanhf((m1 - mean) * inv) / (m1 + 1e-5f);
    float nr0 = r0 * sc0, ni0 = i0 * sc0;
    float nr1 = r1 * sc1, ni1 = i1 * sc1;
    nre[base + tid]       = nr0;
    nim[base + tid]       = ni0;
    nre[base + tid + 256] = nr1;
    nim[base + tid + 256] = ni1;
    // ---- fused diff partials (double; gates the swap only)
    __shared__ double sd[256], sn[256];
    float pr0 = pre[base + tid],       qi0 = pim[base + tid];
    float pr1 = pre[base + tid + 256], qi1 = pim[base + tid + 256];
    float dr0 = nr0 - pr0, di0 = ni0 - qi0;
    float dr1 = nr1 - pr1, di1 = ni1 - qi1;
    sd[tid] = (double)dr0*dr0 + (double)di0*di0 + (double)dr1*dr1 + (double)di1*di1;
    sn[tid] = (double)nr0*nr0 + (double)ni0*ni0 + (double)nr1*nr1 + (double)ni1*ni1;
    __syncthreads();
    for (int s = 128; s > 0; s >>= 1) {
        if (tid < s) { sd[tid] += sd[tid+s]; sn[tid] += sn[tid+s]; }
        __syncthreads();
    }
    if (tid == 0) { g_part_d[row] = sd[0]; g_part_n[row] = sn[0]; }
}

// ---------------------------------------------------------------- flag: reduce partials, swap buffers
__global__ void k_flag() {
    if (!g_active) return;
    const int tid = threadIdx.x;
    double ld = 0.0, lnn = 0.0;
    for (int i = tid; i < NROWS; i += 1024) { ld += g_part_d[i]; lnn += g_part_n[i]; }
    __shared__ double sd[1024], sn[1024];
    sd[tid] = ld; sn[tid] = lnn;
    __syncthreads();
    for (int s = 512; s > 0; s >>= 1) {
        if (tid < s) { sd[tid] += sd[tid+s]; sn[tid] += sn[tid+s]; }
        __syncthreads();
    }
    if (tid == 0) {
        float diff = (float)(sqrt(sd[0]) / (sqrt(sn[0]) + 1e-8));
        g_cur ^= 1;                          // commit = buffer swap (active is known true here)
        if (diff < 1e-3f) g_active = 0;
    }
}

// ---------------------------------------------------------------- mean pool over P
__global__ void k_pool() {
    const float* sre = g_cur ? g_re1 : g_re0;
    const float* sim = g_cur ? g_im1 : g_im0;
    const int idx = blockIdx.x * 256 + threadIdx.x;   // b*D + d
    const int b = idx >> 9, d = idx & (Ddim - 1);
    const size_t base = (size_t)b * Pdim * Ddim + d;
    float accr = 0.0f, acci = 0.0f;
    #pragma unroll 8
    for (int p = 0; p < Pdim; p++) {
        accr += sre[base + (size_t)p * Ddim];
        acci += sim[base + (size_t)p * Ddim];
    }
    g_pool_re[idx] = accr * (1.0f / 256.0f);
    g_pool_im[idx] = acci * (1.0f / 256.0f);
}

// ---------------------------------------------------------------- logits
__global__ void k_logits(float* __restrict__ out, const float* __restrict__ Wr,
                         const float* __restrict__ br, const float* __restrict__ Wi,
                         const float* __restrict__ bi) {
    const int b = blockIdx.x, tid = threadIdx.x;
    float pr0 = g_pool_re[b * Ddim + tid],       pi0 = g_pool_im[b * Ddim + tid];
    float pr1 = g_pool_re[b * Ddim + tid + 256], pi1 = g_pool_im[b * Ddim + tid + 256];
    __shared__ float red[256];
    for (int c = 0; c < Cdim; c++) {
        float v = pr0 * Wr[c * Ddim + tid] + pr1 * Wr[c * Ddim + tid + 256]
                + pi0 * Wi[c * Ddim + tid] + pi1 * Wi[c * Ddim + tid + 256];
        red[tid] = v;
        __syncthreads();
        for (int s = 128; s > 0; s >>= 1) {
            if (tid < s) red[tid] += red[tid+s];
            __syncthreads();
        }
        if (tid == 0) out[b * Cdim + c] = red[0] + br[c] + bi[c];
        __syncthreads();
    }
}

// ---------------------------------------------------------------- launch
extern "C" void kernel_launch(void* const* d_in, const int* in_sizes, int n_in,
                              void* d_out, int out_size) {
    const float* x   = (const float*)d_in[0];
    const float* Wp  = (const float*)d_in[1];
    const float* bp  = (const float*)d_in[2];
    const float* qr  = (const float*)d_in[3];
    const float* kr  = (const float*)d_in[4];
    const float* vr  = (const float*)d_in[5];
    const float* ffr = (const float*)d_in[6];
    const float* ffi = (const float*)d_in[7];
    const float* Wr  = (const float*)d_in[8];
    const float* br  = (const float*)d_in[9];
    const float* Wi  = (const float*)d_in[10];
    const float* bi  = (const float*)d_in[11];
    float* out = (float*)d_out;

    k_prep<<<1, 512>>>(qr, kr, vr);
    k_proj<<<dim3(Ddim/64, (Bdim*Pdim)/64), 256>>>(x, Wp, bp);
    for (int step = 0; step < 4; step++) {
        k_qk<<<dim3(Pdim/64, Pdim/64, Bdim), 256>>>();
        k_softmax<<<Bdim*Pdim, 256>>>();
        k_av<<<dim3(Ddim/64, Pdim/64, Bdim), 256>>>();
        k_ff<<<dim3(Ddim/64, (Bdim*Pdim)/64), 256>>>(ffr, ffi);
        k_norm<<<Bdim*Pdim, 256>>>();
        k_flag<<<1, 1024>>>();
    }
    k_pool<<<(Bdim*Ddim)/256, 256>>>();
    k_logits<<<Bdim, 256>>>(out, Wr, br, Wi, bi);
}

// round 13
// speedup vs baseline: 1.3984x; 1.0349x over previous
#include <cuda_runtime.h>
#include <math.h>

#define Bdim 128
#define Pdim 256
#define PIXdim 256
#define Ddim 512
#define Cdim 10

#define NSTATE (Bdim*Pdim*Ddim)   // 16,777,216
#define NATTN  (Bdim*Pdim*Pdim)   // 8,388,608
#define NROWS  (Bdim*Pdim)        // 32768

static __device__ float g_re0[NSTATE];
static __device__ float g_im0[NSTATE];
static __device__ float g_re1[NSTATE];
static __device__ float g_im1[NSTATE];
static __device__ float g_u_re[NSTATE];
static __device__ float g_u_im[NSTATE];
static __device__ float g_attn[NATTN];
static __device__ float g_pool_re[Bdim*Ddim];
static __device__ float g_pool_im[Bdim*Ddim];
static __device__ float g_cd[Ddim], g_sd[Ddim], g_cv[Ddim], g_sv[Ddim];
static __device__ double g_part_d[NROWS];
static __device__ double g_part_n[NROWS];
static __device__ int g_active;
static __device__ int g_cur;

// ---------------------------------------------------------------- prep
__global__ void k_prep(const float* __restrict__ qr, const float* __restrict__ kr,
                       const float* __restrict__ vr) {
    int d = threadIdx.x;
    if (d < Ddim) {
        float cq, sq, ck, sk, cv, sv;
        sincosf(qr[d], &sq, &cq);
        sincosf(kr[d], &sk, &ck);
        sincosf(vr[d], &sv, &cv);
        g_cd[d] = cq*ck + sq*sk;
        g_sd[d] = sq*ck - cq*sk;
        g_cv[d] = cv;
        g_sv[d] = sv;
    }
    if (d == 0) { g_active = 1; g_cur = 0; }
}

// ---------------------------------------------------------------- proj: state = tanh(x@Wp^T+bp) * e^{i phase}
__global__ void k_proj(const float* __restrict__ x, const float* __restrict__ Wp,
                       const float* __restrict__ bp) {
    __shared__ float As[16][68];
    __shared__ float Bs[16][68];
    const int tid = threadIdx.x;
    const int m0 = blockIdx.y * 64, n0 = blockIdx.x * 64;
    const int tm = (tid >> 4) * 4, tn = (tid & 15) * 4;
    const int lk = tid & 15, lr = tid >> 4;
    float acc[4][4] = {};
    for (int k0 = 0; k0 < PIXdim; k0 += 16) {
        #pragma unroll
        for (int i = 0; i < 4; i++) {
            As[lk][lr + 16*i] = x [(size_t)(m0 + lr + 16*i) * PIXdim + (k0 + lk)];
            Bs[lk][lr + 16*i] = Wp[(size_t)(n0 + lr + 16*i) * PIXdim + (k0 + lk)];
        }
        __syncthreads();
        #pragma unroll
        for (int kk = 0; kk < 16; kk++) {
            float a[4], b[4];
            #pragma unroll
            for (int i = 0; i < 4; i++) { a[i] = As[kk][tm+i]; b[i] = Bs[kk][tn+i]; }
            #pragma unroll
            for (int i = 0; i < 4; i++)
                #pragma unroll
                for (int j = 0; j < 4; j++)
                    acc[i][j] = fmaf(a[i], b[j], acc[i][j]);
        }
        __syncthreads();
    }
    const float PI = 3.14159265358979323846f;
    #pragma unroll
    for (int j = 0; j < 4; j++) {
        int n = n0 + tn + j;
        float freq = 1.0f / powf(10000.0f, (float)n / (float)Ddim);
        float bpv = bp[n];
        #pragma unroll
        for (int i = 0; i < 4; i++) {
            int m = m0 + tm + i;
            int p = m & (Pdim - 1);
            float t = tanhf(acc[i][j] + bpv);
            float ph = ((float)p * freq) * PI;
            float s, c;
            sincosf(ph, &s, &c);
            size_t idx = (size_t)m * Ddim + n;
            g_re0[idx] = t * c;
            g_im0[idx] = t * s;
        }
    }
}

// ---------------------------------------------------------------- QK^H * scale + FUSED softmax
// CTA: 64 p-rows x full 256 q-cols; thread 8x8. Per-output k-chains identical to R1.
// Softmax epilogue reproduces the 256-leaf tree pairing of the standalone kernel exactly.
#define QKSM_FLOATS (64*260)          // att staging dominates (GEMM tiles = 10496 < 16640)
#define QKSM_BYTES  (QKSM_FLOATS*4)

__global__ void __launch_bounds__(256, 2) k_qk() {
    if (!g_active) return;
    extern __shared__ float sm[];
    float* Ar = sm;                    // [16][68]
    float* Ai = sm + 16*68;            // [16][68]
    float* Br = sm + 2*16*68;          // [16][260]
    float* Bi = sm + 2*16*68 + 16*260; // [16][260]
    const int tid = threadIdx.x;
    const int b = blockIdx.y;
    const int p0 = blockIdx.x * 64;
    const int tx = tid & 31, ty = tid >> 5;
    const int lk = tid & 15, lr = tid >> 4;
    const float* __restrict__ sre = (g_cur ? g_re1 : g_re0) + (size_t)b * Pdim * Ddim;
    const float* __restrict__ sim = (g_cur ? g_im1 : g_im0) + (size_t)b * Pdim * Ddim;
    float acc[8][8] = {};
    for (int k0 = 0; k0 < Ddim; k0 += 16) {
        int d = k0 + lk;
        float cd = g_cd[d], sd = g_sd[d];
        #pragma unroll
        for (int i = 0; i < 4; i++) {
            int pr = p0 + lr + 16*i;
            float re = sre[(size_t)pr * Ddim + d];
            float im = sim[(size_t)pr * Ddim + d];
            Ar[lk*68 + lr + 16*i] = re * cd - im * sd;
            Ai[lk*68 + lr + 16*i] = re * sd + im * cd;
        }
        #pragma unroll
        for (int i = 0; i < 16; i++) {
            int qq = lr + 16*i;
            Br[lk*260 + qq] = sre[(size_t)qq * Ddim + d];
            Bi[lk*260 + qq] = sim[(size_t)qq * Ddim + d];
        }
        __syncthreads();
        #pragma unroll
        for (int kk = 0; kk < 16; kk++) {
            float ar[8], ai2[8], br[8], bi2[8];
            #pragma unroll
            for (int i = 0; i < 8; i++) {
                ar[i]  = Ar[kk*68 + ty*8 + i];
                ai2[i] = Ai[kk*68 + ty*8 + i];
            }
            #pragma unroll
            for (int j = 0; j < 8; j++) {
                br[j]  = Br[kk*260 + tx*8 + j];
                bi2[j] = Bi[kk*260 + tx*8 + j];
            }
            #pragma unroll
            for (int i = 0; i < 8; i++)
                #pragma unroll
                for (int j = 0; j < 8; j++) {
                    acc[i][j] = fmaf(ar[i],  br[j],  acc[i][j]);
                    acc[i][j] = fmaf(ai2[i], bi2[j], acc[i][j]);
                }
        }
        __syncthreads();
    }
    const float SCALE = 0.3535533905932738f;  // 8/sqrt(512)
    // stage scaled scores (fp32 round — identical to the old gmem store)
    float* att = sm;                   // [64][260], unions over dead GEMM tiles
    #pragma unroll
    for (int i = 0; i < 8; i++)
        #pragma unroll
        for (int j = 0; j < 8; j++)
            att[(ty*8 + i)*260 + tx*8 + j] = acc[i][j] * SCALE;
    __syncthreads();
    // softmax: one warp per row; exact 256-leaf tree pairing of the standalone kernel
    const int lane = tid & 31, wrp = tid >> 5;
    float* out = g_attn + (size_t)b * Pdim * Pdim;
    #pragma unroll 1
    for (int pass = 0; pass < 8; pass++) {
        int r = pass * 8 + wrp;
        float v[8];
        #pragma unroll
        for (int c = 0; c < 8; c++) v[c] = att[r*260 + lane + 32*c];
        // max (fmaxf exact under any order)
        float w[8];
        #pragma unroll
        for (int c = 0; c < 8; c++) w[c] = v[c];
        #pragma unroll
        for (int c = 0; c < 4; c++) w[c] = fmaxf(w[c], w[c+4]);
        w[0] = fmaxf(w[0], w[2]); w[1] = fmaxf(w[1], w[3]);
        float m = fmaxf(w[0], w[1]);
        #pragma unroll
        for (int s = 16; s > 0; s >>= 1)
            m = fmaxf(m, __shfl_down_sync(0xffffffffu, m, s));
        float mx = __shfl_sync(0xffffffffu, m, 0);
        float e[8];
        #pragma unroll
        for (int c = 0; c < 8; c++) e[c] = expf(v[c] - mx);
        // sum tree: t[c]+=t[c+4] == red[l]+=red[l+128] positions; then +64; then +32; then shfl 16..1
        float t[8];
        #pragma unroll
        for (int c = 0; c < 8; c++) t[c] = e[c];
        #pragma unroll
        for (int c = 0; c < 4; c++) t[c] += t[c+4];
        t[0] += t[2]; t[1] += t[3];
        float s0 = t[0] + t[1];
        #pragma unroll
        for (int s = 16; s > 0; s >>= 1)
            s0 += __shfl_down_sync(0xffffffffu, s0, s);
        float sum = __shfl_sync(0xffffffffu, s0, 0);
        #pragma unroll
        for (int c = 0; c < 8; c++)
            out[(size_t)(p0 + r) * Pdim + lane + 32*c] = e[c] / sum;
    }
}

// ---------------------------------------------------------------- u = prev + e^{iv} * (attn @ state) (R1 core verbatim)
__global__ void k_av() {
    if (!g_active) return;
    __shared__ float As[16][68];
    __shared__ float Br[16][64], Bi[16][64];
    const int tid = threadIdx.x;
    const int b = blockIdx.z;
    const int p0 = blockIdx.y * 64, n0 = blockIdx.x * 64;
    const int tm = (tid >> 4) * 4, tn = (tid & 15) * 4;
    const int lk = tid & 15, lr = tid >> 4;
    const int ln = tid & 63, lkb = tid >> 6;
    const float* __restrict__ sre = (g_cur ? g_re1 : g_re0) + (size_t)b * Pdim * Ddim;
    const float* __restrict__ sim = (g_cur ? g_im1 : g_im0) + (size_t)b * Pdim * Ddim;
    const float* __restrict__ at  = g_attn + (size_t)b * Pdim * Pdim;
    float ar[4][4] = {}, ai[4][4] = {};
    for (int k0 = 0; k0 < Pdim; k0 += 16) {
        #pragma unroll
        for (int i = 0; i < 4; i++)
            As[lk][lr + 16*i] = at[(size_t)(p0 + lr + 16*i) * Pdim + (k0 + lk)];
        #pragma unroll
        for (int i = 0; i < 4; i++) {
            int kq = k0 + lkb * 4 + i;
            Br[lkb*4 + i][ln] = sre[(size_t)kq * Ddim + n0 + ln];
            Bi[lkb*4 + i][ln] = sim[(size_t)kq * Ddim + n0 + ln];
        }
        __syncthreads();
        #pragma unroll
        for (int kk = 0; kk < 16; kk++) {
            float a[4], br[4], bi[4];
            #pragma unroll
            for (int i = 0; i < 4; i++) {
                a[i]  = As[kk][tm+i];
                br[i] = Br[kk][tn+i];
                bi[i] = Bi[kk][tn+i];
            }
            #pragma unroll
            for (int i = 0; i < 4; i++)
                #pragma unroll
                for (int j = 0; j < 4; j++) {
                    ar[i][j] = fmaf(a[i], br[j], ar[i][j]);
                    ai[i][j] = fmaf(a[i], bi[j], ai[i][j]);
                }
        }
        __syncthreads();
    }
    #pragma unroll
    for (int j = 0; j < 4; j++) {
        int d = n0 + tn + j;
        float cv = g_cv[d], sv = g_sv[d];
        #pragma unroll
        for (int i = 0; i < 4; i++) {
            int p = p0 + tm + i;
            size_t idx = (size_t)b * Pdim * Ddim + (size_t)p * Ddim + d;
            float tr = ar[i][j], ti = ai[i][j];
            g_u_re[idx] = sre[(size_t)p * Ddim + d] + cv * tr - sv * ti;
            g_u_im[idx] = sim[(size_t)p * Ddim + d] + sv * tr + cv * ti;
        }
    }
}

// ---------------------------------------------------------------- new = u @ (ffr + i*ffi) (R1 core verbatim)
__global__ void k_ff(const float* __restrict__ ffr, const float* __restrict__ ffi) {
    if (!g_active) return;
    __shared__ float Aur[16][68], Aui[16][68];
    __shared__ float Bfr[16][64], Bfi[16][64];
    const int tid = threadIdx.x;
    const int m0 = blockIdx.y * 64, n0 = blockIdx.x * 64;
    const int tm = (tid >> 4) * 4, tn = (tid & 15) * 4;
    const int lk = tid & 15, lr = tid >> 4;
    const int ln = tid & 63, lkb = tid >> 6;
    float* __restrict__ nre = g_cur ? g_re0 : g_re1;
    float* __restrict__ nim = g_cur ? g_im0 : g_im1;
    float cr[4][4] = {}, ci[4][4] = {};
    for (int k0 = 0; k0 < Ddim; k0 += 16) {
        #pragma unroll
        for (int i = 0; i < 4; i++) {
            size_t ga = (size_t)(m0 + lr + 16*i) * Ddim + (k0 + lk);
            Aur[lk][lr + 16*i] = g_u_re[ga];
            Aui[lk][lr + 16*i] = g_u_im[ga];
        }
        #pragma unroll
        for (int i = 0; i < 4; i++) {
            int kd = k0 + lkb * 4 + i;
            Bfr[lkb*4 + i][ln] = ffr[(size_t)kd * Ddim + n0 + ln];
            Bfi[lkb*4 + i][ln] = ffi[(size_t)kd * Ddim + n0 + ln];
        }
        __syncthreads();
        #pragma unroll
        for (int kk = 0; kk < 16; kk++) {
            float ur[4], ui[4], fr[4], fi[4];
            #pragma unroll
            for (int i = 0; i < 4; i++) {
                ur[i] = Aur[kk][tm+i]; ui[i] = Aui[kk][tm+i];
                fr[i] = Bfr[kk][tn+i]; fi[i] = Bfi[kk][tn+i];
            }
            #pragma unroll
            for (int i = 0; i < 4; i++)
                #pragma unroll
                for (int j = 0; j < 4; j++) {
                    cr[i][j] = fmaf(ur[i],  fr[j], cr[i][j]);
                    cr[i][j] = fmaf(-ui[i], fi[j], cr[i][j]);
                    ci[i][j] = fmaf(ur[i],  fi[j], ci[i][j]);
                    ci[i][j] = fmaf(ui[i],  fr[j], ci[i][j]);
                }
        }
        __syncthreads();
    }
    #pragma unroll
    for (int i = 0; i < 4; i++)
        #pragma unroll
        for (int j = 0; j < 4; j++) {
            size_t idx = (size_t)(m0 + tm + i) * Ddim + (n0 + tn + j);
            nre[idx] = cr[i][j];
            nim[idx] = ci[i][j];
        }
}

// ---------------------------------------------------------------- complex_norm (R1 expressions) + fused diff partials
__global__ void k_norm() {
    if (!g_active) return;
    float* nre = g_cur ? g_re0 : g_re1;
    float* nim = g_cur ? g_im0 : g_im1;
    const float* pre = g_cur ? g_re1 : g_re0;
    const float* pim = g_cur ? g_im1 : g_im0;
    const int row = blockIdx.x;
    const int tid = threadIdx.x;
    const size_t base = (size_t)row * Ddim;
    float r0 = nre[base + tid],       i0 = nim[base + tid];
    float r1 = nre[base + tid + 256], i1 = nim[base + tid + 256];
    float m0 = sqrtf(r0*r0 + i0*i0);
    float m1 = sqrtf(r1*r1 + i1*i1);
    __shared__ float s_sum[256], s_sq[256];
    s_sum[tid] = m0 + m1;
    s_sq[tid]  = m0*m0 + m1*m1;
    __syncthreads();
    for (int s = 128; s > 0; s >>= 1) {
        if (tid < s) { s_sum[tid] += s_sum[tid+s]; s_sq[tid] += s_sq[tid+s]; }
        __syncthreads();
    }
    float mean = s_sum[0] * (1.0f / 512.0f);
    float var  = (s_sq[0] - 512.0f * mean * mean) * (1.0f / 511.0f);
    var = fmaxf(var, 0.0f);
    float inv = 1.0f / (sqrtf(var) + 1e-5f);
    float sc0 = tanhf((m0 - mean) * inv) / (m0 + 1e-5f);
    float sc1 = tanhf((m1 - mean) * inv) / (m1 + 1e-5f);
    float nr0 = r0 * sc0, ni0 = i0 * sc0;
    float nr1 = r1 * sc1, ni1 = i1 * sc1;
    nre[base + tid]       = nr0;
    nim[base + tid]       = ni0;
    nre[base + tid + 256] = nr1;
    nim[base + tid + 256] = ni1;
    __shared__ double sd[256], sn[256];
    float pr0 = pre[base + tid],       qi0 = pim[base + tid];
    float pr1 = pre[base + tid + 256], qi1 = pim[base + tid + 256];
    float dr0 = nr0 - pr0, di0 = ni0 - qi0;
    float dr1 = nr1 - pr1, di1 = ni1 - qi1;
    sd[tid] = (double)dr0*dr0 + (double)di0*di0 + (double)dr1*dr1 + (double)di1*di1;
    sn[tid] = (double)nr0*nr0 + (double)ni0*ni0 + (double)nr1*nr1 + (double)ni1*ni1;
    __syncthreads();
    for (int s = 128; s > 0; s >>= 1) {
        if (tid < s) { sd[tid] += sd[tid+s]; sn[tid] += sn[tid+s]; }
        __syncthreads();
    }
    if (tid == 0) { g_part_d[row] = sd[0]; g_part_n[row] = sn[0]; }
}

// ---------------------------------------------------------------- flag: reduce partials, swap buffers
__global__ void k_flag() {
    if (!g_active) return;
    const int tid = threadIdx.x;
    double ld = 0.0, lnn = 0.0;
    for (int i = tid; i < NROWS; i += 1024) { ld += g_part_d[i]; lnn += g_part_n[i]; }
    __shared__ double sd[1024], sn[1024];
    sd[tid] = ld; sn[tid] = lnn;
    __syncthreads();
    for (int s = 512; s > 0; s >>= 1) {
        if (tid < s) { sd[tid] += sd[tid+s]; sn[tid] += sn[tid+s]; }
        __syncthreads();
    }
    if (tid == 0) {
        float diff = (float)(sqrt(sd[0]) / (sqrt(sn[0]) + 1e-8));
        g_cur ^= 1;                          // commit = buffer swap (active known true here)
        if (diff < 1e-3f) g_active = 0;
    }
}

// ---------------------------------------------------------------- mean pool over P
__global__ void k_pool() {
    const float* sre = g_cur ? g_re1 : g_re0;
    const float* sim = g_cur ? g_im1 : g_im0;
    const int idx = blockIdx.x * 256 + threadIdx.x;   // b*D + d
    const int b = idx >> 9, d = idx & (Ddim - 1);
    const size_t base = (size_t)b * Pdim * Ddim + d;
    float accr = 0.0f, acci = 0.0f;
    #pragma unroll 8
    for (int p = 0; p < Pdim; p++) {
        accr += sre[base + (size_t)p * Ddim];
        acci += sim[base + (size_t)p * Ddim];
    }
    g_pool_re[idx] = accr * (1.0f / 256.0f);
    g_pool_im[idx] = acci * (1.0f / 256.0f);
}

// ---------------------------------------------------------------- logits
__global__ void k_logits(float* __restrict__ out, const float* __restrict__ Wr,
                         const float* __restrict__ br, const float* __restrict__ Wi,
                         const float* __restrict__ bi) {
    const int b = blockIdx.x, tid = threadIdx.x;
    float pr0 = g_pool_re[b * Ddim + tid],       pi0 = g_pool_im[b * Ddim + tid];
    float pr1 = g_pool_re[b * Ddim + tid + 256], pi1 = g_pool_im[b * Ddim + tid + 256];
    __shared__ float red[256];
    for (int c = 0; c < Cdim; c++) {
        float v = pr0 * Wr[c * Ddim + tid] + pr1 * Wr[c * Ddim + tid + 256]
                + pi0 * Wi[c * Ddim + tid] + pi1 * Wi[c * Ddim + tid + 256];
        red[tid] = v;
        __syncthreads();
        for (int s = 128; s > 0; s >>= 1) {
            if (tid < s) red[tid] += red[tid+s];
            __syncthreads();
        }
        if (tid == 0) out[b * Cdim + c] = red[0] + br[c] + bi[c];
        __syncthreads();
    }
}

// ---------------------------------------------------------------- launch
extern "C" void kernel_launch(void* const* d_in, const int* in_sizes, int n_in,
                              void* d_out, int out_size) {
    const float* x   = (const float*)d_in[0];
    const float* Wp  = (const float*)d_in[1];
    const float* bp  = (const float*)d_in[2];
    const float* qr  = (const float*)d_in[3];
    const float* kr  = (const float*)d_in[4];
    const float* vr  = (const float*)d_in[5];
    const float* ffr = (const float*)d_in[6];
    const float* ffi = (const float*)d_in[7];
    const float* Wr  = (const float*)d_in[8];
    const float* br  = (const float*)d_in[9];
    const float* Wi  = (const float*)d_in[10];
    const float* bi  = (const float*)d_in[11];
    float* out = (float*)d_out;

    cudaFuncSetAttribute(k_qk, cudaFuncAttributeMaxDynamicSharedMemorySize, QKSM_BYTES);

    k_prep<<<1, 512>>>(qr, kr, vr);
    k_proj<<<dim3(Ddim/64, (Bdim*Pdim)/64), 256>>>(x, Wp, bp);
    for (int step = 0; step < 4; step++) {
        k_qk<<<dim3(Pdim/64, Bdim), 256, QKSM_BYTES>>>();
        k_av<<<dim3(Ddim/64, Pdim/64, Bdim), 256>>>();
        k_ff<<<dim3(Ddim/64, (Bdim*Pdim)/64), 256>>>(ffr, ffi);
        k_norm<<<Bdim*Pdim, 256>>>();
        k_flag<<<1, 1024>>>();
    }
    k_pool<<<(Bdim*Ddim)/256, 256>>>();
    k_logits<<<Bdim, 256>>>(out, Wr, br, Wi, bi);
}